// round 1
// baseline (speedup 1.0000x reference)
#include <cuda_runtime.h>
#include <math.h>

// Problem constants
#define BATCH 2
#define SEQ   2048
#define DIMM  1024
#define NH    16
#define HD    64
#define INNER 1024          // NH*HD
#define QKV3  3072          // 3*INNER
#define ROWS  4096          // BATCH*SEQ

// Scratch (allocation-free rule: __device__ globals)
__device__ float g_qkv[(size_t)ROWS * QKV3];
__device__ float g_q[(size_t)BATCH * NH * SEQ * HD];
__device__ float g_k[(size_t)BATCH * NH * SEQ * HD];
__device__ float g_v[(size_t)BATCH * NH * SEQ * HD];
__device__ float g_attn[(size_t)ROWS * INNER];

__device__ __forceinline__ float fast_exp2(float x) {
    float y;
    asm("ex2.approx.ftz.f32 %0, %1;" : "=f"(y) : "f"(x));
    return y;
}

// ---------------------------------------------------------------------------
// SGEMM: C[M,N] = A[M,K] @ B[K,N] + bias[N]
// 128x128 tile, BK=8, 256 threads, 8x8 microtile (split 4+4 at +64 offset)
// M,N multiples of 128; K multiple of 8.
// ---------------------------------------------------------------------------
__global__ __launch_bounds__(256) void sgemm128(
    const float* __restrict__ A, const float* __restrict__ B,
    const float* __restrict__ bias, float* __restrict__ C,
    int M, int N, int K)
{
    __shared__ float As[8][128];
    __shared__ float Bs[8][128];

    const int tid = threadIdx.x;
    const int bx = blockIdx.x * 128;
    const int by = blockIdx.y * 128;

    const int aRow = tid & 127;
    const int aCol = (tid >> 7) * 4;          // 0 or 4
    const int bRow = tid >> 5;                // 0..7
    const int bCol = (tid & 31) * 4;          // 0..124

    const int tx = (tid & 15) * 4;            // 0..60
    const int ty = (tid >> 4) * 4;            // 0..60

    float acc[8][8];
#pragma unroll
    for (int i = 0; i < 8; i++)
#pragma unroll
        for (int j = 0; j < 8; j++) acc[i][j] = 0.f;

    const float* Aptr = A + (size_t)(by + aRow) * K + aCol;
    const float* Bptr = B + (size_t)bRow * N + bx + bCol;

    for (int kk = 0; kk < K; kk += 8) {
        float4 av = *(const float4*)(Aptr + kk);
        As[aCol + 0][aRow] = av.x;
        As[aCol + 1][aRow] = av.y;
        As[aCol + 2][aRow] = av.z;
        As[aCol + 3][aRow] = av.w;
        *(float4*)&Bs[bRow][bCol] = *(const float4*)(Bptr + (size_t)kk * N);
        __syncthreads();

#pragma unroll
        for (int k = 0; k < 8; k++) {
            float a[8], bb[8];
            *(float4*)(a)      = *(const float4*)&As[k][ty];
            *(float4*)(a + 4)  = *(const float4*)&As[k][ty + 64];
            *(float4*)(bb)     = *(const float4*)&Bs[k][tx];
            *(float4*)(bb + 4) = *(const float4*)&Bs[k][tx + 64];
#pragma unroll
            for (int i = 0; i < 8; i++)
#pragma unroll
                for (int j = 0; j < 8; j++)
                    acc[i][j] = fmaf(a[i], bb[j], acc[i][j]);
        }
        __syncthreads();
    }

#pragma unroll
    for (int i = 0; i < 8; i++) {
        int r = by + ((i < 4) ? (ty + i) : (ty + 64 + i - 4));
        float* crow = C + (size_t)r * N;
#pragma unroll
        for (int jh = 0; jh < 2; jh++) {
            int c = bx + tx + jh * 64;
            float4 ov;
            ov.x = acc[i][jh * 4 + 0] + bias[c + 0];
            ov.y = acc[i][jh * 4 + 1] + bias[c + 1];
            ov.z = acc[i][jh * 4 + 2] + bias[c + 2];
            ov.w = acc[i][jh * 4 + 3] + bias[c + 3];
            *(float4*)(crow + c) = ov;
        }
    }
}

// ---------------------------------------------------------------------------
// Preprocess: RMSNorm(q,k over inner=1024) + RoPE + history key scale,
// transpose to [B,H,S,D]. One block per token row, 256 threads.
// ---------------------------------------------------------------------------
__global__ __launch_bounds__(256) void preprocess_kernel(
    const float* __restrict__ qkv, const float* __restrict__ rot,
    const float* __restrict__ nqw, const float* __restrict__ nkw,
    const float* __restrict__ hks, const int* __restrict__ oclp,
    float* __restrict__ gq, float* __restrict__ gk, float* __restrict__ gv)
{
    const int row = blockIdx.x;
    const int b = row >> 11;          // /2048
    const int s = row & 2047;
    const int tid = threadIdx.x;
    const float* base = qkv + (size_t)row * QKV3;

    float sq = 0.f, sk = 0.f;
#pragma unroll
    for (int it = 0; it < 4; it++) {
        int i = tid + it * 256;
        float qv = base[i];
        float kv = base[INNER + i];
        sq = fmaf(qv, qv, sq);
        sk = fmaf(kv, kv, sk);
    }
#pragma unroll
    for (int off = 16; off > 0; off >>= 1) {
        sq += __shfl_xor_sync(0xffffffffu, sq, off);
        sk += __shfl_xor_sync(0xffffffffu, sk, off);
    }
    __shared__ float rq[8], rk[8];
    const int wid = tid >> 5, lane = tid & 31;
    if (lane == 0) { rq[wid] = sq; rk[wid] = sk; }
    __syncthreads();
    float tq = 0.f, tk = 0.f;
#pragma unroll
    for (int w = 0; w < 8; w++) { tq += rq[w]; tk += rk[w]; }
    const float invq = rsqrtf(tq * (1.f / 1024.f) + 1e-5f);
    const float invk = rsqrtf(tk * (1.f / 1024.f) + 1e-5f);

    const int hist = SEQ - *oclp;
    const float* rrow = rot + (size_t)row * (2 * HD);

#pragma unroll
    for (int it = 0; it < 2; it++) {
        int p = tid + it * 256;       // pair index 0..511
        int hh = p >> 5;              // head
        int i = p & 31;               // pair-within-head
        int e0 = hh * HD + 2 * i;
        int e1 = e0 + 1;
        float ce = rrow[2 * i];
        float so = rrow[HD + 2 * i + 1];
        float q0 = base[e0] * invq * nqw[e0];
        float q1 = base[e1] * invq * nqw[e1];
        float k0 = base[INNER + e0] * invk * nkw[e0];
        float k1 = base[INNER + e1] * invk * nkw[e1];
        float qo0 = q0 * ce - q1 * so;
        float qo1 = q0 * so + q1 * ce;
        float ko0 = k0 * ce - k1 * so;
        float ko1 = k0 * so + k1 * ce;
        float ksc = 1.f;
        if (s < hist) {
            float hv = hks[hh];
            float sig = 1.f / (1.f + __expf(-hv));
            ksc = 1.f + sig * 9.f;    // MAX_SCALE-1 = 9
        }
        size_t dst = (((size_t)b * NH + hh) * SEQ + s) * HD + 2 * i;
        gq[dst]     = qo0;
        gq[dst + 1] = qo1;
        gk[dst]     = ko0 * ksc;
        gk[dst + 1] = ko1 * ksc;
    }
#pragma unroll
    for (int it = 0; it < 4; it++) {
        int d = tid + it * 256;
        int hh = d >> 6;
        int dd = d & 63;
        gv[(((size_t)b * NH + hh) * SEQ + s) * HD + dd] = base[2 * INNER + d];
    }
}

// ---------------------------------------------------------------------------
// Flash attention (non-causal, full S=2048 keys), fp32.
// 128 queries / block, 1 query / thread. K/V tiles of 64 keys in smem.
// q and o (64 each) in registers; online softmax in chunks of 8 keys.
// ---------------------------------------------------------------------------
__global__ __launch_bounds__(128) void attn_kernel(
    const float* __restrict__ gq, const float* __restrict__ gk,
    const float* __restrict__ gv, float* __restrict__ gout)
{
    const int tid = threadIdx.x;
    const int h = blockIdx.y;
    const int b = blockIdx.z;
    const int q = blockIdx.x * 128 + tid;
    const size_t bh = ((size_t)b * NH + h) * SEQ;

    const float CSCALE = 0.125f * 1.4426950408889634f;  // 1/sqrt(64) * log2(e)

    float qr[64];
    {
        const float4* qp = (const float4*)(gq + (bh + q) * HD);
#pragma unroll
        for (int i = 0; i < 16; i++) {
            float4 v = qp[i];
            qr[4 * i + 0] = v.x * CSCALE;
            qr[4 * i + 1] = v.y * CSCALE;
            qr[4 * i + 2] = v.z * CSCALE;
            qr[4 * i + 3] = v.w * CSCALE;
        }
    }

    __shared__ float Ks[64 * 64];
    __shared__ float Vs[64 * 64];

    float o[64];
#pragma unroll
    for (int d = 0; d < 64; d++) o[d] = 0.f;
    float m = -1e30f, l = 0.f;

    const float4* kg = (const float4*)(gk + bh * HD);
    const float4* vg = (const float4*)(gv + bh * HD);

    for (int kt = 0; kt < SEQ / 64; kt++) {
        __syncthreads();
#pragma unroll
        for (int i = 0; i < 8; i++) {
            ((float4*)Ks)[tid + i * 128] = kg[(size_t)kt * 1024 + tid + i * 128];
            ((float4*)Vs)[tid + i * 128] = vg[(size_t)kt * 1024 + tid + i * 128];
        }
        __syncthreads();

        for (int jc = 0; jc < 8; jc++) {        // 8 chunks of 8 keys
            float sc[8];
#pragma unroll
            for (int j = 0; j < 8; j++) {
                const float4* kr = (const float4*)&Ks[(jc * 8 + j) * 64];
                float a0 = 0.f, a1 = 0.f, a2 = 0.f, a3 = 0.f;
#pragma unroll
                for (int d = 0; d < 16; d++) {
                    float4 kv = kr[d];
                    a0 = fmaf(qr[4 * d + 0], kv.x, a0);
                    a1 = fmaf(qr[4 * d + 1], kv.y, a1);
                    a2 = fmaf(qr[4 * d + 2], kv.z, a2);
                    a3 = fmaf(qr[4 * d + 3], kv.w, a3);
                }
                sc[j] = (a0 + a1) + (a2 + a3);
            }
            float cm = fmaxf(fmaxf(fmaxf(sc[0], sc[1]), fmaxf(sc[2], sc[3])),
                             fmaxf(fmaxf(sc[4], sc[5]), fmaxf(sc[6], sc[7])));
            float mnew = fmaxf(m, cm);
            float corr = fast_exp2(m - mnew);
            l *= corr;
#pragma unroll
            for (int d = 0; d < 64; d++) o[d] *= corr;
#pragma unroll
            for (int j = 0; j < 8; j++) {
                float p = fast_exp2(sc[j] - mnew);
                l += p;
                const float4* vr = (const float4*)&Vs[(jc * 8 + j) * 64];
#pragma unroll
                for (int d = 0; d < 16; d++) {
                    float4 vv = vr[d];
                    o[4 * d + 0] = fmaf(p, vv.x, o[4 * d + 0]);
                    o[4 * d + 1] = fmaf(p, vv.y, o[4 * d + 1]);
                    o[4 * d + 2] = fmaf(p, vv.z, o[4 * d + 2]);
                    o[4 * d + 3] = fmaf(p, vv.w, o[4 * d + 3]);
                }
            }
            m = mnew;
        }
    }

    const float inv = 1.f / l;
    float* op = g_attn + ((size_t)b * SEQ + q) * INNER + h * HD;
#pragma unroll
    for (int i = 0; i < 16; i++) {
        float4 ov;
        ov.x = o[4 * i + 0] * inv;
        ov.y = o[4 * i + 1] * inv;
        ov.z = o[4 * i + 2] * inv;
        ov.w = o[4 * i + 3] * inv;
        ((float4*)op)[i] = ov;
    }
    (void)gout;
}

// ---------------------------------------------------------------------------
extern "C" void kernel_launch(void* const* d_in, const int* in_sizes, int n_in,
                              void* d_out, int out_size)
{
    const float* hidden = (const float*)d_in[0];
    const float* rot    = (const float*)d_in[1];
    const float* w_qkv  = (const float*)d_in[2];
    const float* b_qkv  = (const float*)d_in[3];
    const float* nqw    = (const float*)d_in[4];
    const float* nkw    = (const float*)d_in[5];
    const float* w_out  = (const float*)d_in[6];
    const float* b_out  = (const float*)d_in[7];
    const float* hks    = (const float*)d_in[8];
    const int*   ocl    = (const int*)d_in[9];
    float* out = (float*)d_out;

    static float *p_qkv = nullptr, *p_q = nullptr, *p_k = nullptr,
                 *p_v = nullptr, *p_attn = nullptr;
    if (!p_qkv) {
        cudaGetSymbolAddress((void**)&p_qkv,  g_qkv);
        cudaGetSymbolAddress((void**)&p_q,    g_q);
        cudaGetSymbolAddress((void**)&p_k,    g_k);
        cudaGetSymbolAddress((void**)&p_v,    g_v);
        cudaGetSymbolAddress((void**)&p_attn, g_attn);
    }

    // 1) QKV projection: [4096,1024] @ [1024,3072] + bias
    sgemm128<<<dim3(QKV3 / 128, ROWS / 128), 256>>>(
        hidden, w_qkv, b_qkv, p_qkv, ROWS, QKV3, DIMM);

    // 2) RMSNorm + RoPE + history scale + transpose to [B,H,S,D]
    preprocess_kernel<<<ROWS, 256>>>(p_qkv, rot, nqw, nkw, hks, ocl,
                                     p_q, p_k, p_v);

    // 3) Attention -> g_attn [B,S,INNER]
    attn_kernel<<<dim3(SEQ / 128, NH, BATCH), 128>>>(p_q, p_k, p_v, p_attn);

    // 4) Output projection: [4096,1024] @ [1024,1024] + bias
    sgemm128<<<dim3(DIMM / 128, ROWS / 128), 256>>>(
        p_attn, w_out, b_out, out, ROWS, DIMM, DIMM);
}

// round 3
// speedup vs baseline: 1.6407x; 1.6407x over previous
#include <cuda_runtime.h>
#include <cuda_bf16.h>
#include <math.h>

// Problem constants
#define BATCH 2
#define SEQ   2048
#define DIMM  1024
#define NH    16
#define HD    64
#define INNER 1024          // NH*HD
#define QKV3  3072          // 3*INNER
#define ROWS  4096          // BATCH*SEQ
#define NTILES 32           // SEQ/64

// Scratch (allocation-free rule: __device__ globals)
__device__ float g_qkv[(size_t)ROWS * QKV3];
__device__ float g_q[(size_t)BATCH * NH * SEQ * HD];
__device__ float g_k[(size_t)BATCH * NH * SEQ * HD];
__device__ float g_v[(size_t)BATCH * NH * SEQ * HD];
__device__ float g_attn[(size_t)ROWS * INNER];

// Packed bf16 hi/lo K,V in MMA-slot layout: [b][h][tile][row64][64] bf16
// = 2*16*32*4096 bf16 = 8MB each; as uint4: 524288 each.
#define TILE_U4 512          // 4096 bf16 / 8 per uint4
__device__ uint4 g_khi4[(size_t)BATCH * NH * NTILES * TILE_U4];
__device__ uint4 g_klo4[(size_t)BATCH * NH * NTILES * TILE_U4];
__device__ uint4 g_vhi4[(size_t)BATCH * NH * NTILES * TILE_U4];
__device__ uint4 g_vlo4[(size_t)BATCH * NH * NTILES * TILE_U4];

__device__ __forceinline__ float fast_exp2(float x) {
    float y;
    asm("ex2.approx.ftz.f32 %0, %1;" : "=f"(y) : "f"(x));
    return y;
}

// Split two fp32 into packed bf16x2 hi and bf16x2 lo (x -> low half).
__device__ __forceinline__ void pack_split(float x, float y,
                                           unsigned& hi, unsigned& lo) {
    asm("cvt.rn.bf16x2.f32 %0, %1, %2;" : "=r"(hi) : "f"(y), "f"(x));
    __nv_bfloat162 hb = *(__nv_bfloat162*)&hi;
    float rx = x - __bfloat162float(hb.x);
    float ry = y - __bfloat162float(hb.y);
    asm("cvt.rn.bf16x2.f32 %0, %1, %2;" : "=r"(lo) : "f"(ry), "f"(rx));
}

// bf16 mma m16n8k16, fp32 accumulate
__device__ __forceinline__ void mma_bf16(float d[4], const unsigned a[4],
                                         uint2 b) {
    asm volatile(
        "mma.sync.aligned.m16n8k16.row.col.f32.bf16.bf16.f32 "
        "{%0,%1,%2,%3}, {%4,%5,%6,%7}, {%8,%9}, {%0,%1,%2,%3};"
        : "+f"(d[0]), "+f"(d[1]), "+f"(d[2]), "+f"(d[3])
        : "r"(a[0]), "r"(a[1]), "r"(a[2]), "r"(a[3]), "r"(b.x), "r"(b.y));
}

// ---------------------------------------------------------------------------
// SGEMM: C[M,N] = A[M,K] @ B[K,N] + bias[N]  (proven R1 version, unchanged)
// ---------------------------------------------------------------------------
__global__ __launch_bounds__(256) void sgemm128(
    const float* __restrict__ A, const float* __restrict__ B,
    const float* __restrict__ bias, float* __restrict__ C,
    int M, int N, int K)
{
    __shared__ float As[8][128];
    __shared__ float Bs[8][128];

    const int tid = threadIdx.x;
    const int bx = blockIdx.x * 128;
    const int by = blockIdx.y * 128;

    const int aRow = tid & 127;
    const int aCol = (tid >> 7) * 4;
    const int bRow = tid >> 5;
    const int bCol = (tid & 31) * 4;

    const int tx = (tid & 15) * 4;
    const int ty = (tid >> 4) * 4;

    float acc[8][8];
#pragma unroll
    for (int i = 0; i < 8; i++)
#pragma unroll
        for (int j = 0; j < 8; j++) acc[i][j] = 0.f;

    const float* Aptr = A + (size_t)(by + aRow) * K + aCol;
    const float* Bptr = B + (size_t)bRow * N + bx + bCol;

    for (int kk = 0; kk < K; kk += 8) {
        float4 av = *(const float4*)(Aptr + kk);
        As[aCol + 0][aRow] = av.x;
        As[aCol + 1][aRow] = av.y;
        As[aCol + 2][aRow] = av.z;
        As[aCol + 3][aRow] = av.w;
        *(float4*)&Bs[bRow][bCol] = *(const float4*)(Bptr + (size_t)kk * N);
        __syncthreads();

#pragma unroll
        for (int k = 0; k < 8; k++) {
            float a[8], bb[8];
            *(float4*)(a)      = *(const float4*)&As[k][ty];
            *(float4*)(a + 4)  = *(const float4*)&As[k][ty + 64];
            *(float4*)(bb)     = *(const float4*)&Bs[k][tx];
            *(float4*)(bb + 4) = *(const float4*)&Bs[k][tx + 64];
#pragma unroll
            for (int i = 0; i < 8; i++)
#pragma unroll
                for (int j = 0; j < 8; j++)
                    acc[i][j] = fmaf(a[i], bb[j], acc[i][j]);
        }
        __syncthreads();
    }

#pragma unroll
    for (int i = 0; i < 8; i++) {
        int r = by + ((i < 4) ? (ty + i) : (ty + 64 + i - 4));
        float* crow = C + (size_t)r * N;
#pragma unroll
        for (int jh = 0; jh < 2; jh++) {
            int c = bx + tx + jh * 64;
            float4 ov;
            ov.x = acc[i][jh * 4 + 0] + bias[c + 0];
            ov.y = acc[i][jh * 4 + 1] + bias[c + 1];
            ov.z = acc[i][jh * 4 + 2] + bias[c + 2];
            ov.w = acc[i][jh * 4 + 3] + bias[c + 3];
            *(float4*)(crow + c) = ov;
        }
    }
}

// ---------------------------------------------------------------------------
// Preprocess: RMSNorm + RoPE + history key scale, transpose to [B,H,S,D]
// (proven R1 version, unchanged)
// ---------------------------------------------------------------------------
__global__ __launch_bounds__(256) void preprocess_kernel(
    const float* __restrict__ qkv, const float* __restrict__ rot,
    const float* __restrict__ nqw, const float* __restrict__ nkw,
    const float* __restrict__ hks, const int* __restrict__ oclp,
    float* __restrict__ gq, float* __restrict__ gk, float* __restrict__ gv)
{
    const int row = blockIdx.x;
    const int b = row >> 11;
    const int s = row & 2047;
    const int tid = threadIdx.x;
    const float* base = qkv + (size_t)row * QKV3;

    float sq = 0.f, sk = 0.f;
#pragma unroll
    for (int it = 0; it < 4; it++) {
        int i = tid + it * 256;
        float qv = base[i];
        float kv = base[INNER + i];
        sq = fmaf(qv, qv, sq);
        sk = fmaf(kv, kv, sk);
    }
#pragma unroll
    for (int off = 16; off > 0; off >>= 1) {
        sq += __shfl_xor_sync(0xffffffffu, sq, off);
        sk += __shfl_xor_sync(0xffffffffu, sk, off);
    }
    __shared__ float rq[8], rk[8];
    const int wid = tid >> 5, lane = tid & 31;
    if (lane == 0) { rq[wid] = sq; rk[wid] = sk; }
    __syncthreads();
    float tq = 0.f, tk = 0.f;
#pragma unroll
    for (int w = 0; w < 8; w++) { tq += rq[w]; tk += rk[w]; }
    const float invq = rsqrtf(tq * (1.f / 1024.f) + 1e-5f);
    const float invk = rsqrtf(tk * (1.f / 1024.f) + 1e-5f);

    const int hist = SEQ - *oclp;
    const float* rrow = rot + (size_t)row * (2 * HD);

#pragma unroll
    for (int it = 0; it < 2; it++) {
        int p = tid + it * 256;
        int hh = p >> 5;
        int i = p & 31;
        int e0 = hh * HD + 2 * i;
        int e1 = e0 + 1;
        float ce = rrow[2 * i];
        float so = rrow[HD + 2 * i + 1];
        float q0 = base[e0] * invq * nqw[e0];
        float q1 = base[e1] * invq * nqw[e1];
        float k0 = base[INNER + e0] * invk * nkw[e0];
        float k1 = base[INNER + e1] * invk * nkw[e1];
        float qo0 = q0 * ce - q1 * so;
        float qo1 = q0 * so + q1 * ce;
        float ko0 = k0 * ce - k1 * so;
        float ko1 = k0 * so + k1 * ce;
        float ksc = 1.f;
        if (s < hist) {
            float hv = hks[hh];
            float sig = 1.f / (1.f + __expf(-hv));
            ksc = 1.f + sig * 9.f;
        }
        size_t dst = (((size_t)b * NH + hh) * SEQ + s) * HD + 2 * i;
        gq[dst]     = qo0;
        gq[dst + 1] = qo1;
        gk[dst]     = ko0 * ksc;
        gk[dst + 1] = ko1 * ksc;
    }
#pragma unroll
    for (int it = 0; it < 4; it++) {
        int d = tid + it * 256;
        int hh = d >> 6;
        int dd = d & 63;
        gv[(((size_t)b * NH + hh) * SEQ + s) * HD + dd] = base[2 * INNER + d];
    }
}

// ---------------------------------------------------------------------------
// Pack K,V into bf16 hi/lo, MMA-slot-swizzled tiles.
// Slot layout per 64-wide row: slot sg = c*4+tig (4 bf16 = 8B) holds elements
// {16c+2tig, 16c+2tig+1, 16c+2tig+8, 16c+2tig+9} of the row.
// K rows = keys (elements = d). V rows = d (elements = keys, i.e. transposed).
// One block per (tile, h, b).
// ---------------------------------------------------------------------------
__global__ __launch_bounds__(256) void pack_kv_kernel(
    const float* __restrict__ gk, const float* __restrict__ gv)
{
    const int kt = blockIdx.x, h = blockIdx.y, b = blockIdx.z;
    const int tid = threadIdx.x;
    const size_t tb = ((size_t)(b * NH + h) * NTILES + kt);
    const float* ksrc = gk + ((size_t)(b * NH + h) * SEQ + kt * 64) * HD;
    const float* vsrc = gv + ((size_t)(b * NH + h) * SEQ + kt * 64) * HD;

    __shared__ float Vsm[64][68];
#pragma unroll
    for (int i = 0; i < 4; i++) {
        int idx = tid + 256 * i;          // 1024 float4 = 64x64 floats
        int row = idx >> 4, c4 = idx & 15;
        *(float4*)&Vsm[row][c4 * 4] = ((const float4*)vsrc)[idx];
    }
    __syncthreads();

    const int r = tid >> 2;               // 0..63 (key for K, d for V)
    const int grp = tid & 3;              // c chunk

    uint2* khid = (uint2*)(g_khi4 + tb * TILE_U4) + r * 16;
    uint2* klod = (uint2*)(g_klo4 + tb * TILE_U4) + r * 16;
    uint2* vhid = (uint2*)(g_vhi4 + tb * TILE_U4) + r * 16;
    uint2* vlod = (uint2*)(g_vlo4 + tb * TILE_U4) + r * 16;

    const float* krow = ksrc + r * HD;
#pragma unroll
    for (int tig = 0; tig < 4; tig++) {
        int d0 = grp * 16 + 2 * tig;
        // K: row = key r, elements along d
        float2 p0 = *(const float2*)(krow + d0);
        float2 p1 = *(const float2*)(krow + d0 + 8);
        unsigned h0, l0, h1, l1;
        pack_split(p0.x, p0.y, h0, l0);
        pack_split(p1.x, p1.y, h1, l1);
        khid[grp * 4 + tig] = make_uint2(h0, h1);
        klod[grp * 4 + tig] = make_uint2(l0, l1);
        // V transposed: row = d r, elements along key
        float v0 = Vsm[d0][r], v1 = Vsm[d0 + 1][r];
        float v2 = Vsm[d0 + 8][r], v3 = Vsm[d0 + 9][r];
        pack_split(v0, v1, h0, l0);
        pack_split(v2, v3, h1, l1);
        vhid[grp * 4 + tig] = make_uint2(h0, h1);
        vlod[grp * 4 + tig] = make_uint2(l0, l1);
    }
}

// ---------------------------------------------------------------------------
// Flash attention, bf16x3 emulated-fp32 on tensor cores (mma m16n8k16).
// 8 warps x 16 q rows = 128 queries/block; 64-key K/V tiles in smem.
// Smem rows padded to 72 bf16 (144B) -> conflict-free LDS.64 B-frag reads.
// Accumulator layout of S == A-fragment layout for P (k16): no shuffles.
// ---------------------------------------------------------------------------
#define SMSTRIDE 72

__global__ __launch_bounds__(256, 2) void attn_tc_kernel(
    const float* __restrict__ gq)
{
    __shared__ __align__(16) __nv_bfloat16 Khi[64 * SMSTRIDE];
    __shared__ __align__(16) __nv_bfloat16 Klo[64 * SMSTRIDE];
    __shared__ __align__(16) __nv_bfloat16 Vhi[64 * SMSTRIDE];
    __shared__ __align__(16) __nv_bfloat16 Vlo[64 * SMSTRIDE];

    const int tid  = threadIdx.x;
    const int w    = tid >> 5;
    const int lane = tid & 31;
    const int g    = lane >> 2;     // 0..7
    const int tig  = lane & 3;      // 0..3
    const int h = blockIdx.y, b = blockIdx.z;
    const int qb = blockIdx.x * 128;
    const size_t bh = ((size_t)b * NH + h) * SEQ;

    const float SC = 0.125f * 1.4426950408889634f;  // 1/sqrt(64) * log2(e)

    // Q A-fragments (hi/lo), kept in regs. Slab c covers d = 16c..16c+15.
    unsigned qhi[4][4], qlo[4][4];
    {
        const float* q0 = gq + (bh + qb + w * 16 + g) * HD;
        const float* q1 = q0 + 8 * HD;
#pragma unroll
        for (int c = 0; c < 4; c++) {
            int d0 = 16 * c + 2 * tig;
            float2 f00 = *(const float2*)(q0 + d0);      // a0: row g,   k lo
            float2 f10 = *(const float2*)(q1 + d0);      // a1: row g+8, k lo
            float2 f01 = *(const float2*)(q0 + d0 + 8);  // a2: row g,   k hi
            float2 f11 = *(const float2*)(q1 + d0 + 8);  // a3: row g+8, k hi
            pack_split(f00.x * SC, f00.y * SC, qhi[c][0], qlo[c][0]);
            pack_split(f10.x * SC, f10.y * SC, qhi[c][1], qlo[c][1]);
            pack_split(f01.x * SC, f01.y * SC, qhi[c][2], qlo[c][2]);
            pack_split(f11.x * SC, f11.y * SC, qhi[c][3], qlo[c][3]);
        }
    }

    float o[8][4];
#pragma unroll
    for (int nt = 0; nt < 8; nt++)
#pragma unroll
        for (int i = 0; i < 4; i++) o[nt][i] = 0.f;
    float m0 = -1e30f, m1 = -1e30f, l0 = 0.f, l1 = 0.f;

    const size_t tbase = ((size_t)(b * NH + h) * NTILES) * TILE_U4;

    for (int kt = 0; kt < NTILES; kt++) {
        __syncthreads();
        const size_t tb = tbase + (size_t)kt * TILE_U4;
#pragma unroll
        for (int i = 0; i < 2; i++) {
            int idx = tid + 256 * i;      // 512 uint4 per array
            int row = idx >> 3, ch = idx & 7;
            int so = row * SMSTRIDE + ch * 8;
            *(uint4*)&Khi[so] = g_khi4[tb + idx];
            *(uint4*)&Klo[so] = g_klo4[tb + idx];
            *(uint4*)&Vhi[so] = g_vhi4[tb + idx];
            *(uint4*)&Vlo[so] = g_vlo4[tb + idx];
        }
        __syncthreads();

        // S = Q @ K^T (16 x 64 per warp), bf16x3
        float s[8][4];
#pragma unroll
        for (int jn = 0; jn < 8; jn++) {
#pragma unroll
            for (int i = 0; i < 4; i++) s[jn][i] = 0.f;
            const uint2* krh = (const uint2*)&Khi[(jn * 8 + g) * SMSTRIDE];
            const uint2* krl = (const uint2*)&Klo[(jn * 8 + g) * SMSTRIDE];
#pragma unroll
            for (int c = 0; c < 4; c++) {
                uint2 bh_ = krh[c * 4 + tig];
                uint2 bl_ = krl[c * 4 + tig];
                mma_bf16(s[jn], qhi[c], bh_);
                mma_bf16(s[jn], qlo[c], bh_);
                mma_bf16(s[jn], qhi[c], bl_);
            }
        }

        // Online softmax (log2 domain; SC folded into Q)
        float rmax0 = s[0][0], rmax1 = s[0][2];
#pragma unroll
        for (int jn = 0; jn < 8; jn++) {
            rmax0 = fmaxf(rmax0, fmaxf(s[jn][0], s[jn][1]));
            rmax1 = fmaxf(rmax1, fmaxf(s[jn][2], s[jn][3]));
        }
        rmax0 = fmaxf(rmax0, __shfl_xor_sync(0xffffffffu, rmax0, 1));
        rmax0 = fmaxf(rmax0, __shfl_xor_sync(0xffffffffu, rmax0, 2));
        rmax1 = fmaxf(rmax1, __shfl_xor_sync(0xffffffffu, rmax1, 1));
        rmax1 = fmaxf(rmax1, __shfl_xor_sync(0xffffffffu, rmax1, 2));

        float mn0 = fmaxf(m0, rmax0);
        float mn1 = fmaxf(m1, rmax1);
        float corr0 = fast_exp2(m0 - mn0);
        float corr1 = fast_exp2(m1 - mn1);
        m0 = mn0; m1 = mn1;

        float ps0 = 0.f, ps1 = 0.f;
#pragma unroll
        for (int jn = 0; jn < 8; jn++) {
            s[jn][0] = fast_exp2(s[jn][0] - mn0);
            s[jn][1] = fast_exp2(s[jn][1] - mn0);
            s[jn][2] = fast_exp2(s[jn][2] - mn1);
            s[jn][3] = fast_exp2(s[jn][3] - mn1);
            ps0 += s[jn][0] + s[jn][1];
            ps1 += s[jn][2] + s[jn][3];
        }
        l0 = l0 * corr0 + ps0;
        l1 = l1 * corr1 + ps1;
#pragma unroll
        for (int nt = 0; nt < 8; nt++) {
            o[nt][0] *= corr0;
            o[nt][1] *= corr0;
            o[nt][2] *= corr1;
            o[nt][3] *= corr1;
        }

        // P split to bf16 hi/lo A-fragments. Slab c = keys 16c..16c+15.
        // Accumulator cols (2tig,2tig+1) of block jn map directly to A k-pairs.
        unsigned phi[4][4], plo[4][4];
#pragma unroll
        for (int c = 0; c < 4; c++) {
            pack_split(s[2 * c][0],     s[2 * c][1],     phi[c][0], plo[c][0]);
            pack_split(s[2 * c][2],     s[2 * c][3],     phi[c][1], plo[c][1]);
            pack_split(s[2 * c + 1][0], s[2 * c + 1][1], phi[c][2], plo[c][2]);
            pack_split(s[2 * c + 1][2], s[2 * c + 1][3], phi[c][3], plo[c][3]);
        }

        // O += P @ V, bf16x3
#pragma unroll
        for (int nt = 0; nt < 8; nt++) {
            const uint2* vrh = (const uint2*)&Vhi[(nt * 8 + g) * SMSTRIDE];
            const uint2* vrl = (const uint2*)&Vlo[(nt * 8 + g) * SMSTRIDE];
#pragma unroll
            for (int c = 0; c < 4; c++) {
                uint2 bh_ = vrh[c * 4 + tig];
                uint2 bl_ = vrl[c * 4 + tig];
                mma_bf16(o[nt], phi[c], bh_);
                mma_bf16(o[nt], plo[c], bh_);
                mma_bf16(o[nt], phi[c], bl_);
            }
        }
    }

    // Final normalize + write to g_attn [B,S,INNER]
    l0 += __shfl_xor_sync(0xffffffffu, l0, 1);
    l0 += __shfl_xor_sync(0xffffffffu, l0, 2);
    l1 += __shfl_xor_sync(0xffffffffu, l1, 1);
    l1 += __shfl_xor_sync(0xffffffffu, l1, 2);
    const float inv0 = 1.f / l0;
    const float inv1 = 1.f / l1;

    float* orow0 = g_attn + ((size_t)b * SEQ + qb + w * 16 + g) * INNER + h * HD;
    float* orow1 = orow0 + 8 * INNER;
#pragma unroll
    for (int nt = 0; nt < 8; nt++) {
        float2 a, c;
        a.x = o[nt][0] * inv0; a.y = o[nt][1] * inv0;
        c.x = o[nt][2] * inv1; c.y = o[nt][3] * inv1;
        *(float2*)(orow0 + 8 * nt + 2 * tig) = a;
        *(float2*)(orow1 + 8 * nt + 2 * tig) = c;
    }
}

// ---------------------------------------------------------------------------
extern "C" void kernel_launch(void* const* d_in, const int* in_sizes, int n_in,
                              void* d_out, int out_size)
{
    const float* hidden = (const float*)d_in[0];
    const float* rot    = (const float*)d_in[1];
    const float* w_qkv  = (const float*)d_in[2];
    const float* b_qkv  = (const float*)d_in[3];
    const float* nqw    = (const float*)d_in[4];
    const float* nkw    = (const float*)d_in[5];
    const float* w_out  = (const float*)d_in[6];
    const float* b_out  = (const float*)d_in[7];
    const float* hks    = (const float*)d_in[8];
    const int*   ocl    = (const int*)d_in[9];
    float* out = (float*)d_out;

    static float *p_qkv = nullptr, *p_q = nullptr, *p_k = nullptr,
                 *p_v = nullptr, *p_attn = nullptr;
    if (!p_qkv) {
        cudaGetSymbolAddress((void**)&p_qkv,  g_qkv);
        cudaGetSymbolAddress((void**)&p_q,    g_q);
        cudaGetSymbolAddress((void**)&p_k,    g_k);
        cudaGetSymbolAddress((void**)&p_v,    g_v);
        cudaGetSymbolAddress((void**)&p_attn, g_attn);
    }

    // 1) QKV projection
    sgemm128<<<dim3(QKV3 / 128, ROWS / 128), 256>>>(
        hidden, w_qkv, b_qkv, p_qkv, ROWS, QKV3, DIMM);

    // 2) RMSNorm + RoPE + history scale + transpose
    preprocess_kernel<<<ROWS, 256>>>(p_qkv, rot, nqw, nkw, hks, ocl,
                                     p_q, p_k, p_v);

    // 3) Pack K,V to bf16 hi/lo MMA tiles
    pack_kv_kernel<<<dim3(NTILES, NH, BATCH), 256>>>(p_k, p_v);

    // 4) Attention (bf16x3 tensor cores) -> g_attn
    attn_tc_kernel<<<dim3(SEQ / 128, NH, BATCH), 256>>>(p_q);

    // 5) Output projection
    sgemm128<<<dim3(DIMM / 128, ROWS / 128), 256>>>(
        p_attn, w_out, b_out, out, ROWS, DIMM, DIMM);
}

// round 4
// speedup vs baseline: 2.9489x; 1.7974x over previous
#include <cuda_runtime.h>
#include <cuda_bf16.h>
#include <math.h>

// Problem constants
#define BATCH 2
#define SEQ   2048
#define DIMM  1024
#define NH    16
#define HD    64
#define INNER 1024          // NH*HD
#define QKV3  3072          // 3*INNER
#define ROWS  4096          // BATCH*SEQ
#define NTILES 32           // SEQ/64
#define NKI   32            // GEMM K iterations (K=1024, 32 per iter)

// Scratch (allocation-free rule: __device__ globals)
__device__ float g_qkv[(size_t)ROWS * QKV3];
__device__ float g_q[(size_t)BATCH * NH * SEQ * HD];
__device__ float g_k[(size_t)BATCH * NH * SEQ * HD];
__device__ float g_v[(size_t)BATCH * NH * SEQ * HD];
__device__ float g_attn[(size_t)ROWS * INNER];

// Attention packed KV tiles
#define TILE_U4 512          // 4096 bf16 / 8 per uint4
__device__ uint4 g_khi4[(size_t)BATCH * NH * NTILES * TILE_U4];
__device__ uint4 g_klo4[(size_t)BATCH * NH * NTILES * TILE_U4];
__device__ uint4 g_vhi4[(size_t)BATCH * NH * NTILES * TILE_U4];
__device__ uint4 g_vlo4[(size_t)BATCH * NH * NTILES * TILE_U4];

// GEMM packed operands.
// A pack: per (mt, ki): 512 hi uint4 then 512 lo uint4 (slot layout).
__device__ uint4 g_apack[(size_t)32 * NKI * 1024];       // mt = 4096/128 = 32
// B pack: per (nt, ki): 1024 uint4, each = {hi.x, hi.y, lo.x, lo.y}.
__device__ uint4 g_bpack_qkv[(size_t)24 * NKI * 1024];   // nt = 3072/128
__device__ uint4 g_bpack_out[(size_t)8  * NKI * 1024];   // nt = 1024/128

__device__ __forceinline__ float fast_exp2(float x) {
    float y;
    asm("ex2.approx.ftz.f32 %0, %1;" : "=f"(y) : "f"(x));
    return y;
}

// Split two fp32 into packed bf16x2 hi and bf16x2 lo (x -> low half).
__device__ __forceinline__ void pack_split(float x, float y,
                                           unsigned& hi, unsigned& lo) {
    asm("cvt.rn.bf16x2.f32 %0, %1, %2;" : "=r"(hi) : "f"(y), "f"(x));
    __nv_bfloat162 hb = *(__nv_bfloat162*)&hi;
    float rx = x - __bfloat162float(hb.x);
    float ry = y - __bfloat162float(hb.y);
    asm("cvt.rn.bf16x2.f32 %0, %1, %2;" : "=r"(lo) : "f"(ry), "f"(rx));
}

// bf16 mma m16n8k16, fp32 accumulate
__device__ __forceinline__ void mma_bf16(float d[4], const unsigned a[4],
                                         uint2 b) {
    asm volatile(
        "mma.sync.aligned.m16n8k16.row.col.f32.bf16.bf16.f32 "
        "{%0,%1,%2,%3}, {%4,%5,%6,%7}, {%8,%9}, {%0,%1,%2,%3};"
        : "+f"(d[0]), "+f"(d[1]), "+f"(d[2]), "+f"(d[3])
        : "r"(a[0]), "r"(a[1]), "r"(a[2]), "r"(a[3]), "r"(b.x), "r"(b.y));
}

// ---------------------------------------------------------------------------
// Pack A [M x 1024] fp32 row-major into MMA A-fragment slot layout.
// Slot s (0..511): mb=s>>6, ks=(s>>5)&1, lane=s&31 (g=lane>>2, t=lane&3).
// hi uint4 = {A[r0][k0,k0+1], A[r0+8][k0,k0+1], A[r0][k0+8,+9], A[r0+8][k0+8,+9]}
// with r0 = mt*128+mb*16+g, k0 = ki*32+ks*16+2t. lo = residual.
// ---------------------------------------------------------------------------
__global__ __launch_bounds__(256) void pack_a_kernel(const float* __restrict__ A)
{
    const int ki = blockIdx.x, mt = blockIdx.y;
    uint4* dst = g_apack + ((size_t)(mt * NKI + ki)) * 1024;
#pragma unroll
    for (int j = 0; j < 2; j++) {
        int s = threadIdx.x + j * 256;
        int mb = s >> 6, ks = (s >> 5) & 1, lane = s & 31;
        int g = lane >> 2, t = lane & 3;
        const float* r0 = A + (size_t)(mt * 128 + mb * 16 + g) * 1024
                            + ki * 32 + ks * 16 + 2 * t;
        const float* r1 = r0 + 8 * 1024;
        float2 f00 = *(const float2*)r0;
        float2 f10 = *(const float2*)r1;
        float2 f01 = *(const float2*)(r0 + 8);
        float2 f11 = *(const float2*)(r1 + 8);
        uint4 hi, lo;
        pack_split(f00.x, f00.y, hi.x, lo.x);
        pack_split(f10.x, f10.y, hi.y, lo.y);
        pack_split(f01.x, f01.y, hi.z, lo.z);
        pack_split(f11.x, f11.y, hi.w, lo.w);
        dst[s]       = hi;
        dst[512 + s] = lo;
    }
}

// ---------------------------------------------------------------------------
// Pack B [1024 x N] fp32 row-major into MMA B-fragment slot layout.
// Slot s (0..1023): nb=s>>6, ks=(s>>5)&1, lane=s&31 (g, t).
// uint4 = {hi(B[kk][n],B[kk+1][n]), hi(B[kk+8][n],B[kk+9][n]), lo, lo}
// with n = nt*128+nb*8+g, kk = ki*32+ks*16+2t.
// ---------------------------------------------------------------------------
__global__ __launch_bounds__(256) void pack_b_kernel(
    const float* __restrict__ B, uint4* __restrict__ dst0, int N)
{
    const int ki = blockIdx.x, nt = blockIdx.y;
    uint4* dst = dst0 + ((size_t)(nt * NKI + ki)) * 1024;
#pragma unroll
    for (int j = 0; j < 4; j++) {
        int s = threadIdx.x + j * 256;
        int nb = s >> 6, ks = (s >> 5) & 1, lane = s & 31;
        int g = lane >> 2, t = lane & 3;
        int n = nt * 128 + nb * 8 + g;
        int kk = ki * 32 + ks * 16 + 2 * t;
        const float* p = B + (size_t)kk * N + n;
        float b0 = p[0];
        float b1 = p[N];
        float b2 = p[8 * (size_t)N];
        float b3 = p[9 * (size_t)N];
        uint4 v;
        pack_split(b0, b1, v.x, v.z);
        pack_split(b2, b3, v.y, v.w);
        dst[s] = v;
    }
}

// ---------------------------------------------------------------------------
// bf16x3 GEMM: C[M,N] = A@B + bias, from packed operands.
// Block 256 thr (8 warps as 4x2), tile 128x128, K-step 32.
// Warp tile 32x64: 2 m-blocks x 8 n-blocks of m16n8k16, x3 emulation.
// ---------------------------------------------------------------------------
__global__ __launch_bounds__(256, 2) void gemm_bf16x3(
    const uint4* __restrict__ gB, const float* __restrict__ bias,
    float* __restrict__ C, int N)
{
    __shared__ uint4 sA[1024];   // 512 hi + 512 lo
    __shared__ uint4 sB[1024];   // combined hi/lo

    const int tid = threadIdx.x;
    const int w = tid >> 5, lane = tid & 31;
    const int g = lane >> 2, t = lane & 3;
    const int wm = w >> 1, wn = w & 1;
    const int nt = blockIdx.x, mt = blockIdx.y;

    const uint4* aSrc = g_apack + (size_t)(mt * NKI) * 1024;
    const uint4* bSrc = gB + (size_t)(nt * NKI) * 1024;

    float acc[2][8][4];
#pragma unroll
    for (int mb = 0; mb < 2; mb++)
#pragma unroll
        for (int nb = 0; nb < 8; nb++)
#pragma unroll
            for (int i = 0; i < 4; i++) acc[mb][nb][i] = 0.f;

    for (int ki = 0; ki < NKI; ki++) {
        __syncthreads();
#pragma unroll
        for (int j = 0; j < 4; j++) {
            sA[tid + j * 256] = aSrc[(size_t)ki * 1024 + tid + j * 256];
            sB[tid + j * 256] = bSrc[(size_t)ki * 1024 + tid + j * 256];
        }
        __syncthreads();

#pragma unroll
        for (int ks = 0; ks < 2; ks++) {
            unsigned ah[2][4], al[2][4];
#pragma unroll
            for (int mb = 0; mb < 2; mb++) {
                int slot = (wm * 2 + mb) * 64 + ks * 32 + lane;
                uint4 hv = sA[slot];
                uint4 lv = sA[512 + slot];
                ah[mb][0] = hv.x; ah[mb][1] = hv.y;
                ah[mb][2] = hv.z; ah[mb][3] = hv.w;
                al[mb][0] = lv.x; al[mb][1] = lv.y;
                al[mb][2] = lv.z; al[mb][3] = lv.w;
            }
#pragma unroll
            for (int nb = 0; nb < 8; nb++) {
                int slot = (wn * 8 + nb) * 64 + ks * 32 + lane;
                uint4 bv = sB[slot];
                uint2 bh = make_uint2(bv.x, bv.y);
                uint2 bl = make_uint2(bv.z, bv.w);
#pragma unroll
                for (int mb = 0; mb < 2; mb++) {
                    mma_bf16(acc[mb][nb], ah[mb], bh);
                    mma_bf16(acc[mb][nb], al[mb], bh);
                    mma_bf16(acc[mb][nb], ah[mb], bl);
                }
            }
        }
    }

    // Epilogue: acc c0,c1 -> (row g, cols 2t,2t+1); c2,c3 -> row g+8.
#pragma unroll
    for (int mb = 0; mb < 2; mb++) {
        int r0 = mt * 128 + wm * 32 + mb * 16 + g;
#pragma unroll
        for (int nb = 0; nb < 8; nb++) {
            int c = nt * 128 + wn * 64 + nb * 8 + 2 * t;
            float bx = bias[c], by = bias[c + 1];
            float2 v0, v1;
            v0.x = acc[mb][nb][0] + bx; v0.y = acc[mb][nb][1] + by;
            v1.x = acc[mb][nb][2] + bx; v1.y = acc[mb][nb][3] + by;
            *(float2*)(C + (size_t)r0 * N + c)       = v0;
            *(float2*)(C + (size_t)(r0 + 8) * N + c) = v1;
        }
    }
}

// ---------------------------------------------------------------------------
// Preprocess: RMSNorm + RoPE + history key scale, transpose to [B,H,S,D]
// (proven, unchanged)
// ---------------------------------------------------------------------------
__global__ __launch_bounds__(256) void preprocess_kernel(
    const float* __restrict__ qkv, const float* __restrict__ rot,
    const float* __restrict__ nqw, const float* __restrict__ nkw,
    const float* __restrict__ hks, const int* __restrict__ oclp,
    float* __restrict__ gq, float* __restrict__ gk, float* __restrict__ gv)
{
    const int row = blockIdx.x;
    const int b = row >> 11;
    const int s = row & 2047;
    const int tid = threadIdx.x;
    const float* base = qkv + (size_t)row * QKV3;

    float sq = 0.f, sk = 0.f;
#pragma unroll
    for (int it = 0; it < 4; it++) {
        int i = tid + it * 256;
        float qv = base[i];
        float kv = base[INNER + i];
        sq = fmaf(qv, qv, sq);
        sk = fmaf(kv, kv, sk);
    }
#pragma unroll
    for (int off = 16; off > 0; off >>= 1) {
        sq += __shfl_xor_sync(0xffffffffu, sq, off);
        sk += __shfl_xor_sync(0xffffffffu, sk, off);
    }
    __shared__ float rq[8], rk[8];
    const int wid = tid >> 5, lane = tid & 31;
    if (lane == 0) { rq[wid] = sq; rk[wid] = sk; }
    __syncthreads();
    float tq = 0.f, tk = 0.f;
#pragma unroll
    for (int w = 0; w < 8; w++) { tq += rq[w]; tk += rk[w]; }
    const float invq = rsqrtf(tq * (1.f / 1024.f) + 1e-5f);
    const float invk = rsqrtf(tk * (1.f / 1024.f) + 1e-5f);

    const int hist = SEQ - *oclp;
    const float* rrow = rot + (size_t)row * (2 * HD);

#pragma unroll
    for (int it = 0; it < 2; it++) {
        int p = tid + it * 256;
        int hh = p >> 5;
        int i = p & 31;
        int e0 = hh * HD + 2 * i;
        int e1 = e0 + 1;
        float ce = rrow[2 * i];
        float so = rrow[HD + 2 * i + 1];
        float q0 = base[e0] * invq * nqw[e0];
        float q1 = base[e1] * invq * nqw[e1];
        float k0 = base[INNER + e0] * invk * nkw[e0];
        float k1 = base[INNER + e1] * invk * nkw[e1];
        float qo0 = q0 * ce - q1 * so;
        float qo1 = q0 * so + q1 * ce;
        float ko0 = k0 * ce - k1 * so;
        float ko1 = k0 * so + k1 * ce;
        float ksc = 1.f;
        if (s < hist) {
            float hv = hks[hh];
            float sig = 1.f / (1.f + __expf(-hv));
            ksc = 1.f + sig * 9.f;
        }
        size_t dst = (((size_t)b * NH + hh) * SEQ + s) * HD + 2 * i;
        gq[dst]     = qo0;
        gq[dst + 1] = qo1;
        gk[dst]     = ko0 * ksc;
        gk[dst + 1] = ko1 * ksc;
    }
#pragma unroll
    for (int it = 0; it < 4; it++) {
        int d = tid + it * 256;
        int hh = d >> 6;
        int dd = d & 63;
        gv[(((size_t)b * NH + hh) * SEQ + s) * HD + dd] = base[2 * INNER + d];
    }
}

// ---------------------------------------------------------------------------
// Pack K,V into bf16 hi/lo MMA-slot tiles (proven, unchanged)
// ---------------------------------------------------------------------------
__global__ __launch_bounds__(256) void pack_kv_kernel(
    const float* __restrict__ gk, const float* __restrict__ gv)
{
    const int kt = blockIdx.x, h = blockIdx.y, b = blockIdx.z;
    const int tid = threadIdx.x;
    const size_t tb = ((size_t)(b * NH + h) * NTILES + kt);
    const float* ksrc = gk + ((size_t)(b * NH + h) * SEQ + kt * 64) * HD;
    const float* vsrc = gv + ((size_t)(b * NH + h) * SEQ + kt * 64) * HD;

    __shared__ float Vsm[64][68];
#pragma unroll
    for (int i = 0; i < 4; i++) {
        int idx = tid + 256 * i;
        int row = idx >> 4, c4 = idx & 15;
        *(float4*)&Vsm[row][c4 * 4] = ((const float4*)vsrc)[idx];
    }
    __syncthreads();

    const int r = tid >> 2;
    const int grp = tid & 3;

    uint2* khid = (uint2*)(g_khi4 + tb * TILE_U4) + r * 16;
    uint2* klod = (uint2*)(g_klo4 + tb * TILE_U4) + r * 16;
    uint2* vhid = (uint2*)(g_vhi4 + tb * TILE_U4) + r * 16;
    uint2* vlod = (uint2*)(g_vlo4 + tb * TILE_U4) + r * 16;

    const float* krow = ksrc + r * HD;
#pragma unroll
    for (int tig = 0; tig < 4; tig++) {
        int d0 = grp * 16 + 2 * tig;
        float2 p0 = *(const float2*)(krow + d0);
        float2 p1 = *(const float2*)(krow + d0 + 8);
        unsigned h0, l0, h1, l1;
        pack_split(p0.x, p0.y, h0, l0);
        pack_split(p1.x, p1.y, h1, l1);
        khid[grp * 4 + tig] = make_uint2(h0, h1);
        klod[grp * 4 + tig] = make_uint2(l0, l1);
        float v0 = Vsm[d0][r], v1 = Vsm[d0 + 1][r];
        float v2 = Vsm[d0 + 8][r], v3 = Vsm[d0 + 9][r];
        pack_split(v0, v1, h0, l0);
        pack_split(v2, v3, h1, l1);
        vhid[grp * 4 + tig] = make_uint2(h0, h1);
        vlod[grp * 4 + tig] = make_uint2(l0, l1);
    }
}

// ---------------------------------------------------------------------------
// Flash attention, bf16x3 on tensor cores (proven, unchanged)
// ---------------------------------------------------------------------------
#define SMSTRIDE 72

__global__ __launch_bounds__(256, 2) void attn_tc_kernel(
    const float* __restrict__ gq)
{
    __shared__ __align__(16) __nv_bfloat16 Khi[64 * SMSTRIDE];
    __shared__ __align__(16) __nv_bfloat16 Klo[64 * SMSTRIDE];
    __shared__ __align__(16) __nv_bfloat16 Vhi[64 * SMSTRIDE];
    __shared__ __align__(16) __nv_bfloat16 Vlo[64 * SMSTRIDE];

    const int tid  = threadIdx.x;
    const int w    = tid >> 5;
    const int lane = tid & 31;
    const int g    = lane >> 2;
    const int tig  = lane & 3;
    const int h = blockIdx.y, b = blockIdx.z;
    const int qb = blockIdx.x * 128;
    const size_t bh = ((size_t)b * NH + h) * SEQ;

    const float SC = 0.125f * 1.4426950408889634f;

    unsigned qhi[4][4], qlo[4][4];
    {
        const float* q0 = gq + (bh + qb + w * 16 + g) * HD;
        const float* q1 = q0 + 8 * HD;
#pragma unroll
        for (int c = 0; c < 4; c++) {
            int d0 = 16 * c + 2 * tig;
            float2 f00 = *(const float2*)(q0 + d0);
            float2 f10 = *(const float2*)(q1 + d0);
            float2 f01 = *(const float2*)(q0 + d0 + 8);
            float2 f11 = *(const float2*)(q1 + d0 + 8);
            pack_split(f00.x * SC, f00.y * SC, qhi[c][0], qlo[c][0]);
            pack_split(f10.x * SC, f10.y * SC, qhi[c][1], qlo[c][1]);
            pack_split(f01.x * SC, f01.y * SC, qhi[c][2], qlo[c][2]);
            pack_split(f11.x * SC, f11.y * SC, qhi[c][3], qlo[c][3]);
        }
    }

    float o[8][4];
#pragma unroll
    for (int nt = 0; nt < 8; nt++)
#pragma unroll
        for (int i = 0; i < 4; i++) o[nt][i] = 0.f;
    float m0 = -1e30f, m1 = -1e30f, l0 = 0.f, l1 = 0.f;

    const size_t tbase = ((size_t)(b * NH + h) * NTILES) * TILE_U4;

    for (int kt = 0; kt < NTILES; kt++) {
        __syncthreads();
        const size_t tb = tbase + (size_t)kt * TILE_U4;
#pragma unroll
        for (int i = 0; i < 2; i++) {
            int idx = tid + 256 * i;
            int row = idx >> 3, ch = idx & 7;
            int so = row * SMSTRIDE + ch * 8;
            *(uint4*)&Khi[so] = g_khi4[tb + idx];
            *(uint4*)&Klo[so] = g_klo4[tb + idx];
            *(uint4*)&Vhi[so] = g_vhi4[tb + idx];
            *(uint4*)&Vlo[so] = g_vlo4[tb + idx];
        }
        __syncthreads();

        float s[8][4];
#pragma unroll
        for (int jn = 0; jn < 8; jn++) {
#pragma unroll
            for (int i = 0; i < 4; i++) s[jn][i] = 0.f;
            const uint2* krh = (const uint2*)&Khi[(jn * 8 + g) * SMSTRIDE];
            const uint2* krl = (const uint2*)&Klo[(jn * 8 + g) * SMSTRIDE];
#pragma unroll
            for (int c = 0; c < 4; c++) {
                uint2 bh_ = krh[c * 4 + tig];
                uint2 bl_ = krl[c * 4 + tig];
                mma_bf16(s[jn], qhi[c], bh_);
                mma_bf16(s[jn], qlo[c], bh_);
                mma_bf16(s[jn], qhi[c], bl_);
            }
        }

        float rmax0 = s[0][0], rmax1 = s[0][2];
#pragma unroll
        for (int jn = 0; jn < 8; jn++) {
            rmax0 = fmaxf(rmax0, fmaxf(s[jn][0], s[jn][1]));
            rmax1 = fmaxf(rmax1, fmaxf(s[jn][2], s[jn][3]));
        }
        rmax0 = fmaxf(rmax0, __shfl_xor_sync(0xffffffffu, rmax0, 1));
        rmax0 = fmaxf(rmax0, __shfl_xor_sync(0xffffffffu, rmax0, 2));
        rmax1 = fmaxf(rmax1, __shfl_xor_sync(0xffffffffu, rmax1, 1));
        rmax1 = fmaxf(rmax1, __shfl_xor_sync(0xffffffffu, rmax1, 2));

        float mn0 = fmaxf(m0, rmax0);
        float mn1 = fmaxf(m1, rmax1);
        float corr0 = fast_exp2(m0 - mn0);
        float corr1 = fast_exp2(m1 - mn1);
        m0 = mn0; m1 = mn1;

        float ps0 = 0.f, ps1 = 0.f;
#pragma unroll
        for (int jn = 0; jn < 8; jn++) {
            s[jn][0] = fast_exp2(s[jn][0] - mn0);
            s[jn][1] = fast_exp2(s[jn][1] - mn0);
            s[jn][2] = fast_exp2(s[jn][2] - mn1);
            s[jn][3] = fast_exp2(s[jn][3] - mn1);
            ps0 += s[jn][0] + s[jn][1];
            ps1 += s[jn][2] + s[jn][3];
        }
        l0 = l0 * corr0 + ps0;
        l1 = l1 * corr1 + ps1;
#pragma unroll
        for (int nt = 0; nt < 8; nt++) {
            o[nt][0] *= corr0;
            o[nt][1] *= corr0;
            o[nt][2] *= corr1;
            o[nt][3] *= corr1;
        }

        unsigned phi[4][4], plo[4][4];
#pragma unroll
        for (int c = 0; c < 4; c++) {
            pack_split(s[2 * c][0],     s[2 * c][1],     phi[c][0], plo[c][0]);
            pack_split(s[2 * c][2],     s[2 * c][3],     phi[c][1], plo[c][1]);
            pack_split(s[2 * c + 1][0], s[2 * c + 1][1], phi[c][2], plo[c][2]);
            pack_split(s[2 * c + 1][2], s[2 * c + 1][3], phi[c][3], plo[c][3]);
        }

#pragma unroll
        for (int nt = 0; nt < 8; nt++) {
            const uint2* vrh = (const uint2*)&Vhi[(nt * 8 + g) * SMSTRIDE];
            const uint2* vrl = (const uint2*)&Vlo[(nt * 8 + g) * SMSTRIDE];
#pragma unroll
            for (int c = 0; c < 4; c++) {
                uint2 bh_ = vrh[c * 4 + tig];
                uint2 bl_ = vrl[c * 4 + tig];
                mma_bf16(o[nt], phi[c], bh_);
                mma_bf16(o[nt], plo[c], bh_);
                mma_bf16(o[nt], phi[c], bl_);
            }
        }
    }

    l0 += __shfl_xor_sync(0xffffffffu, l0, 1);
    l0 += __shfl_xor_sync(0xffffffffu, l0, 2);
    l1 += __shfl_xor_sync(0xffffffffu, l1, 1);
    l1 += __shfl_xor_sync(0xffffffffu, l1, 2);
    const float inv0 = 1.f / l0;
    const float inv1 = 1.f / l1;

    float* orow0 = g_attn + ((size_t)b * SEQ + qb + w * 16 + g) * INNER + h * HD;
    float* orow1 = orow0 + 8 * INNER;
#pragma unroll
    for (int nt = 0; nt < 8; nt++) {
        float2 a, c;
        a.x = o[nt][0] * inv0; a.y = o[nt][1] * inv0;
        c.x = o[nt][2] * inv1; c.y = o[nt][3] * inv1;
        *(float2*)(orow0 + 8 * nt + 2 * tig) = a;
        *(float2*)(orow1 + 8 * nt + 2 * tig) = c;
    }
}

// ---------------------------------------------------------------------------
extern "C" void kernel_launch(void* const* d_in, const int* in_sizes, int n_in,
                              void* d_out, int out_size)
{
    const float* hidden = (const float*)d_in[0];
    const float* rot    = (const float*)d_in[1];
    const float* w_qkv  = (const float*)d_in[2];
    const float* b_qkv  = (const float*)d_in[3];
    const float* nqw    = (const float*)d_in[4];
    const float* nkw    = (const float*)d_in[5];
    const float* w_out  = (const float*)d_in[6];
    const float* b_out  = (const float*)d_in[7];
    const float* hks    = (const float*)d_in[8];
    const int*   ocl    = (const int*)d_in[9];
    float* out = (float*)d_out;

    static float *p_qkv = nullptr, *p_q = nullptr, *p_k = nullptr,
                 *p_v = nullptr, *p_attn = nullptr;
    static uint4 *p_bq = nullptr, *p_bo = nullptr;
    if (!p_qkv) {
        cudaGetSymbolAddress((void**)&p_qkv,  g_qkv);
        cudaGetSymbolAddress((void**)&p_q,    g_q);
        cudaGetSymbolAddress((void**)&p_k,    g_k);
        cudaGetSymbolAddress((void**)&p_v,    g_v);
        cudaGetSymbolAddress((void**)&p_attn, g_attn);
        cudaGetSymbolAddress((void**)&p_bq,   g_bpack_qkv);
        cudaGetSymbolAddress((void**)&p_bo,   g_bpack_out);
    }

    // 1) Pack operands for QKV GEMM
    pack_b_kernel<<<dim3(NKI, QKV3 / 128), 256>>>(w_qkv, p_bq, QKV3);
    pack_b_kernel<<<dim3(NKI, DIMM / 128), 256>>>(w_out, p_bo, DIMM);
    pack_a_kernel<<<dim3(NKI, ROWS / 128), 256>>>(hidden);

    // 2) QKV projection (bf16x3 tensor cores)
    gemm_bf16x3<<<dim3(QKV3 / 128, ROWS / 128), 256>>>(p_bq, b_qkv, p_qkv, QKV3);

    // 3) RMSNorm + RoPE + history scale + transpose
    preprocess_kernel<<<ROWS, 256>>>(p_qkv, rot, nqw, nkw, hks, ocl,
                                     p_q, p_k, p_v);

    // 4) Pack K,V for attention
    pack_kv_kernel<<<dim3(NTILES, NH, BATCH), 256>>>(p_k, p_v);

    // 5) Attention (bf16x3 tensor cores) -> g_attn
    attn_tc_kernel<<<dim3(SEQ / 128, NH, BATCH), 256>>>(p_q);

    // 6) Pack attention output as A for output projection (reuses g_apack)
    pack_a_kernel<<<dim3(NKI, ROWS / 128), 256>>>(p_attn);

    // 7) Output projection (bf16x3 tensor cores)
    gemm_bf16x3<<<dim3(DIMM / 128, ROWS / 128), 256>>>(p_bo, b_out, out, DIMM);
}

// round 5
// speedup vs baseline: 3.1875x; 1.0809x over previous
#include <cuda_runtime.h>
#include <cuda_bf16.h>
#include <math.h>

// Problem constants
#define BATCH 2
#define SEQ   2048
#define DIMM  1024
#define NH    16
#define HD    64
#define INNER 1024          // NH*HD
#define QKV3  3072          // 3*INNER
#define ROWS  4096          // BATCH*SEQ
#define NTILES 32           // SEQ/64
#define NKI   32            // GEMM K iterations (K=1024, 32 per iter)

// Scratch (allocation-free rule: __device__ globals)
__device__ float g_qkv[(size_t)ROWS * QKV3];
__device__ float g_q[(size_t)BATCH * NH * SEQ * HD];
__device__ float g_k[(size_t)BATCH * NH * SEQ * HD];
__device__ float g_v[(size_t)BATCH * NH * SEQ * HD];

// Attention packed KV tiles
#define TILE_U4 512          // 4096 bf16 / 8 per uint4
__device__ uint4 g_khi4[(size_t)BATCH * NH * NTILES * TILE_U4];
__device__ uint4 g_klo4[(size_t)BATCH * NH * NTILES * TILE_U4];
__device__ uint4 g_vhi4[(size_t)BATCH * NH * NTILES * TILE_U4];
__device__ uint4 g_vlo4[(size_t)BATCH * NH * NTILES * TILE_U4];

// GEMM packed operands.
// A pack: per (mt, ki): 512 hi uint4 then 512 lo uint4 (slot layout).
__device__ uint4 g_apack[(size_t)32 * NKI * 1024];       // mt = 4096/128 = 32
// B pack: per (nt, ki): 1024 uint4, each = {hi.x, hi.y, lo.x, lo.y}.
__device__ uint4 g_bpack_qkv[(size_t)24 * NKI * 1024];   // nt = 3072/128
__device__ uint4 g_bpack_out[(size_t)8  * NKI * 1024];   // nt = 1024/128

__device__ __forceinline__ float fast_exp2(float x) {
    float y;
    asm("ex2.approx.ftz.f32 %0, %1;" : "=f"(y) : "f"(x));
    return y;
}

// Split two fp32 into packed bf16x2 hi and bf16x2 lo (x -> low half).
__device__ __forceinline__ void pack_split(float x, float y,
                                           unsigned& hi, unsigned& lo) {
    asm("cvt.rn.bf16x2.f32 %0, %1, %2;" : "=r"(hi) : "f"(y), "f"(x));
    __nv_bfloat162 hb = *(__nv_bfloat162*)&hi;
    float rx = x - __bfloat162float(hb.x);
    float ry = y - __bfloat162float(hb.y);
    asm("cvt.rn.bf16x2.f32 %0, %1, %2;" : "=r"(lo) : "f"(ry), "f"(rx));
}

// bf16 mma m16n8k16, fp32 accumulate
__device__ __forceinline__ void mma_bf16(float d[4], const unsigned a[4],
                                         uint2 b) {
    asm volatile(
        "mma.sync.aligned.m16n8k16.row.col.f32.bf16.bf16.f32 "
        "{%0,%1,%2,%3}, {%4,%5,%6,%7}, {%8,%9}, {%0,%1,%2,%3};"
        : "+f"(d[0]), "+f"(d[1]), "+f"(d[2]), "+f"(d[3])
        : "r"(a[0]), "r"(a[1]), "r"(a[2]), "r"(a[3]), "r"(b.x), "r"(b.y));
}

// ---------------------------------------------------------------------------
// Pack A [M x 1024] fp32 row-major into MMA A-fragment slot layout.
// ---------------------------------------------------------------------------
__global__ __launch_bounds__(256) void pack_a_kernel(const float* __restrict__ A)
{
    const int ki = blockIdx.x, mt = blockIdx.y;
    uint4* dst = g_apack + ((size_t)(mt * NKI + ki)) * 1024;
#pragma unroll
    for (int j = 0; j < 2; j++) {
        int s = threadIdx.x + j * 256;
        int mb = s >> 6, ks = (s >> 5) & 1, lane = s & 31;
        int g = lane >> 2, t = lane & 3;
        const float* r0 = A + (size_t)(mt * 128 + mb * 16 + g) * 1024
                            + ki * 32 + ks * 16 + 2 * t;
        const float* r1 = r0 + 8 * 1024;
        float2 f00 = *(const float2*)r0;
        float2 f10 = *(const float2*)r1;
        float2 f01 = *(const float2*)(r0 + 8);
        float2 f11 = *(const float2*)(r1 + 8);
        uint4 hi, lo;
        pack_split(f00.x, f00.y, hi.x, lo.x);
        pack_split(f10.x, f10.y, hi.y, lo.y);
        pack_split(f01.x, f01.y, hi.z, lo.z);
        pack_split(f11.x, f11.y, hi.w, lo.w);
        dst[s]       = hi;
        dst[512 + s] = lo;
    }
}

// ---------------------------------------------------------------------------
// Pack B [1024 x N] fp32 row-major into MMA B-fragment slot layout.
// ---------------------------------------------------------------------------
__global__ __launch_bounds__(256) void pack_b_kernel(
    const float* __restrict__ B, uint4* __restrict__ dst0, int N)
{
    const int ki = blockIdx.x, nt = blockIdx.y;
    uint4* dst = dst0 + ((size_t)(nt * NKI + ki)) * 1024;
#pragma unroll
    for (int j = 0; j < 4; j++) {
        int s = threadIdx.x + j * 256;
        int nb = s >> 6, ks = (s >> 5) & 1, lane = s & 31;
        int g = lane >> 2, t = lane & 3;
        int n = nt * 128 + nb * 8 + g;
        int kk = ki * 32 + ks * 16 + 2 * t;
        const float* p = B + (size_t)kk * N + n;
        float b0 = p[0];
        float b1 = p[N];
        float b2 = p[8 * (size_t)N];
        float b3 = p[9 * (size_t)N];
        uint4 v;
        pack_split(b0, b1, v.x, v.z);
        pack_split(b2, b3, v.y, v.w);
        dst[s] = v;
    }
}

// ---------------------------------------------------------------------------
// bf16x3 GEMM: C[M,N] = A@B + bias, from packed operands. (proven, unchanged)
// ---------------------------------------------------------------------------
__global__ __launch_bounds__(256, 2) void gemm_bf16x3(
    const uint4* __restrict__ gB, const float* __restrict__ bias,
    float* __restrict__ C, int N)
{
    __shared__ uint4 sA[1024];
    __shared__ uint4 sB[1024];

    const int tid = threadIdx.x;
    const int w = tid >> 5, lane = tid & 31;
    const int g = lane >> 2, t = lane & 3;
    const int wm = w >> 1, wn = w & 1;
    const int nt = blockIdx.x, mt = blockIdx.y;

    const uint4* aSrc = g_apack + (size_t)(mt * NKI) * 1024;
    const uint4* bSrc = gB + (size_t)(nt * NKI) * 1024;

    float acc[2][8][4];
#pragma unroll
    for (int mb = 0; mb < 2; mb++)
#pragma unroll
        for (int nb = 0; nb < 8; nb++)
#pragma unroll
            for (int i = 0; i < 4; i++) acc[mb][nb][i] = 0.f;

    for (int ki = 0; ki < NKI; ki++) {
        __syncthreads();
#pragma unroll
        for (int j = 0; j < 4; j++) {
            sA[tid + j * 256] = aSrc[(size_t)ki * 1024 + tid + j * 256];
            sB[tid + j * 256] = bSrc[(size_t)ki * 1024 + tid + j * 256];
        }
        __syncthreads();

#pragma unroll
        for (int ks = 0; ks < 2; ks++) {
            unsigned ah[2][4], al[2][4];
#pragma unroll
            for (int mb = 0; mb < 2; mb++) {
                int slot = (wm * 2 + mb) * 64 + ks * 32 + lane;
                uint4 hv = sA[slot];
                uint4 lv = sA[512 + slot];
                ah[mb][0] = hv.x; ah[mb][1] = hv.y;
                ah[mb][2] = hv.z; ah[mb][3] = hv.w;
                al[mb][0] = lv.x; al[mb][1] = lv.y;
                al[mb][2] = lv.z; al[mb][3] = lv.w;
            }
#pragma unroll
            for (int nb = 0; nb < 8; nb++) {
                int slot = (wn * 8 + nb) * 64 + ks * 32 + lane;
                uint4 bv = sB[slot];
                uint2 bh = make_uint2(bv.x, bv.y);
                uint2 bl = make_uint2(bv.z, bv.w);
#pragma unroll
                for (int mb = 0; mb < 2; mb++) {
                    mma_bf16(acc[mb][nb], ah[mb], bh);
                    mma_bf16(acc[mb][nb], al[mb], bh);
                    mma_bf16(acc[mb][nb], ah[mb], bl);
                }
            }
        }
    }

#pragma unroll
    for (int mb = 0; mb < 2; mb++) {
        int r0 = mt * 128 + wm * 32 + mb * 16 + g;
#pragma unroll
        for (int nb = 0; nb < 8; nb++) {
            int c = nt * 128 + wn * 64 + nb * 8 + 2 * t;
            float bx = bias[c], by = bias[c + 1];
            float2 v0, v1;
            v0.x = acc[mb][nb][0] + bx; v0.y = acc[mb][nb][1] + by;
            v1.x = acc[mb][nb][2] + bx; v1.y = acc[mb][nb][3] + by;
            *(float2*)(C + (size_t)r0 * N + c)       = v0;
            *(float2*)(C + (size_t)(r0 + 8) * N + c) = v1;
        }
    }
}

// ---------------------------------------------------------------------------
// Preprocess: RMSNorm + RoPE + history key scale, transpose (proven, unchanged)
// ---------------------------------------------------------------------------
__global__ __launch_bounds__(256) void preprocess_kernel(
    const float* __restrict__ qkv, const float* __restrict__ rot,
    const float* __restrict__ nqw, const float* __restrict__ nkw,
    const float* __restrict__ hks, const int* __restrict__ oclp,
    float* __restrict__ gq, float* __restrict__ gk, float* __restrict__ gv)
{
    const int row = blockIdx.x;
    const int b = row >> 11;
    const int s = row & 2047;
    const int tid = threadIdx.x;
    const float* base = qkv + (size_t)row * QKV3;

    float sq = 0.f, sk = 0.f;
#pragma unroll
    for (int it = 0; it < 4; it++) {
        int i = tid + it * 256;
        float qv = base[i];
        float kv = base[INNER + i];
        sq = fmaf(qv, qv, sq);
        sk = fmaf(kv, kv, sk);
    }
#pragma unroll
    for (int off = 16; off > 0; off >>= 1) {
        sq += __shfl_xor_sync(0xffffffffu, sq, off);
        sk += __shfl_xor_sync(0xffffffffu, sk, off);
    }
    __shared__ float rq[8], rk[8];
    const int wid = tid >> 5, lane = tid & 31;
    if (lane == 0) { rq[wid] = sq; rk[wid] = sk; }
    __syncthreads();
    float tq = 0.f, tk = 0.f;
#pragma unroll
    for (int w = 0; w < 8; w++) { tq += rq[w]; tk += rk[w]; }
    const float invq = rsqrtf(tq * (1.f / 1024.f) + 1e-5f);
    const float invk = rsqrtf(tk * (1.f / 1024.f) + 1e-5f);

    const int hist = SEQ - *oclp;
    const float* rrow = rot + (size_t)row * (2 * HD);

#pragma unroll
    for (int it = 0; it < 2; it++) {
        int p = tid + it * 256;
        int hh = p >> 5;
        int i = p & 31;
        int e0 = hh * HD + 2 * i;
        int e1 = e0 + 1;
        float ce = rrow[2 * i];
        float so = rrow[HD + 2 * i + 1];
        float q0 = base[e0] * invq * nqw[e0];
        float q1 = base[e1] * invq * nqw[e1];
        float k0 = base[INNER + e0] * invk * nkw[e0];
        float k1 = base[INNER + e1] * invk * nkw[e1];
        float qo0 = q0 * ce - q1 * so;
        float qo1 = q0 * so + q1 * ce;
        float ko0 = k0 * ce - k1 * so;
        float ko1 = k0 * so + k1 * ce;
        float ksc = 1.f;
        if (s < hist) {
            float hv = hks[hh];
            float sig = 1.f / (1.f + __expf(-hv));
            ksc = 1.f + sig * 9.f;
        }
        size_t dst = (((size_t)b * NH + hh) * SEQ + s) * HD + 2 * i;
        gq[dst]     = qo0;
        gq[dst + 1] = qo1;
        gk[dst]     = ko0 * ksc;
        gk[dst + 1] = ko1 * ksc;
    }
#pragma unroll
    for (int it = 0; it < 4; it++) {
        int d = tid + it * 256;
        int hh = d >> 6;
        int dd = d & 63;
        gv[(((size_t)b * NH + hh) * SEQ + s) * HD + dd] = base[2 * INNER + d];
    }
}

// ---------------------------------------------------------------------------
// Pack K,V into bf16 hi/lo MMA-slot tiles (proven, unchanged)
// ---------------------------------------------------------------------------
__global__ __launch_bounds__(256) void pack_kv_kernel(
    const float* __restrict__ gk, const float* __restrict__ gv)
{
    const int kt = blockIdx.x, h = blockIdx.y, b = blockIdx.z;
    const int tid = threadIdx.x;
    const size_t tb = ((size_t)(b * NH + h) * NTILES + kt);
    const float* ksrc = gk + ((size_t)(b * NH + h) * SEQ + kt * 64) * HD;
    const float* vsrc = gv + ((size_t)(b * NH + h) * SEQ + kt * 64) * HD;

    __shared__ float Vsm[64][68];
#pragma unroll
    for (int i = 0; i < 4; i++) {
        int idx = tid + 256 * i;
        int row = idx >> 4, c4 = idx & 15;
        *(float4*)&Vsm[row][c4 * 4] = ((const float4*)vsrc)[idx];
    }
    __syncthreads();

    const int r = tid >> 2;
    const int grp = tid & 3;

    uint2* khid = (uint2*)(g_khi4 + tb * TILE_U4) + r * 16;
    uint2* klod = (uint2*)(g_klo4 + tb * TILE_U4) + r * 16;
    uint2* vhid = (uint2*)(g_vhi4 + tb * TILE_U4) + r * 16;
    uint2* vlod = (uint2*)(g_vlo4 + tb * TILE_U4) + r * 16;

    const float* krow = ksrc + r * HD;
#pragma unroll
    for (int tig = 0; tig < 4; tig++) {
        int d0 = grp * 16 + 2 * tig;
        float2 p0 = *(const float2*)(krow + d0);
        float2 p1 = *(const float2*)(krow + d0 + 8);
        unsigned h0, l0, h1, l1;
        pack_split(p0.x, p0.y, h0, l0);
        pack_split(p1.x, p1.y, h1, l1);
        khid[grp * 4 + tig] = make_uint2(h0, h1);
        klod[grp * 4 + tig] = make_uint2(l0, l1);
        float v0 = Vsm[d0][r], v1 = Vsm[d0 + 1][r];
        float v2 = Vsm[d0 + 8][r], v3 = Vsm[d0 + 9][r];
        pack_split(v0, v1, h0, l0);
        pack_split(v2, v3, h1, l1);
        vhid[grp * 4 + tig] = make_uint2(h0, h1);
        vlod[grp * 4 + tig] = make_uint2(l0, l1);
    }
}

// ---------------------------------------------------------------------------
// Flash attention, bf16x3 tensor cores. 4 warps x 32 queries = 128 q/CTA.
// Each B-fragment read feeds 2 m-blocks (6 MMAs) -> smem bytes/flop halved.
// Epilogue writes the output-projection A operand DIRECTLY in packed
// hi/lo slot layout (g_apack) -> no g_attn round trip, no pack_a pass.
// ---------------------------------------------------------------------------
#define SMSTRIDE 72

__global__ __launch_bounds__(128, 2) void attn_tc_kernel(
    const float* __restrict__ gq)
{
    __shared__ __align__(16) __nv_bfloat16 Khi[64 * SMSTRIDE];
    __shared__ __align__(16) __nv_bfloat16 Klo[64 * SMSTRIDE];
    __shared__ __align__(16) __nv_bfloat16 Vhi[64 * SMSTRIDE];
    __shared__ __align__(16) __nv_bfloat16 Vlo[64 * SMSTRIDE];

    const int tid  = threadIdx.x;
    const int w    = tid >> 5;      // 0..3
    const int lane = tid & 31;
    const int g    = lane >> 2;     // 0..7
    const int tig  = lane & 3;      // 0..3
    const int h = blockIdx.y, b = blockIdx.z;
    const int qb = blockIdx.x * 128;
    const size_t bh = ((size_t)b * NH + h) * SEQ;

    const float SC = 0.125f * 1.4426950408889634f;  // 1/sqrt(64)*log2(e)

    // Q A-fragments (hi/lo) for 2 m-blocks of 16 rows.
    unsigned qhi[2][4][4], qlo[2][4][4];
#pragma unroll
    for (int mb = 0; mb < 2; mb++) {
        const float* q0 = gq + (bh + qb + w * 32 + mb * 16 + g) * HD;
        const float* q1 = q0 + 8 * HD;
#pragma unroll
        for (int c = 0; c < 4; c++) {
            int d0 = 16 * c + 2 * tig;
            float2 f00 = *(const float2*)(q0 + d0);
            float2 f10 = *(const float2*)(q1 + d0);
            float2 f01 = *(const float2*)(q0 + d0 + 8);
            float2 f11 = *(const float2*)(q1 + d0 + 8);
            pack_split(f00.x * SC, f00.y * SC, qhi[mb][c][0], qlo[mb][c][0]);
            pack_split(f10.x * SC, f10.y * SC, qhi[mb][c][1], qlo[mb][c][1]);
            pack_split(f01.x * SC, f01.y * SC, qhi[mb][c][2], qlo[mb][c][2]);
            pack_split(f11.x * SC, f11.y * SC, qhi[mb][c][3], qlo[mb][c][3]);
        }
    }

    float o[2][8][4];
#pragma unroll
    for (int mb = 0; mb < 2; mb++)
#pragma unroll
        for (int nt = 0; nt < 8; nt++)
#pragma unroll
            for (int i = 0; i < 4; i++) o[mb][nt][i] = 0.f;
    float mst[2][2] = {{-1e30f, -1e30f}, {-1e30f, -1e30f}};
    float lst[2][2] = {{0.f, 0.f}, {0.f, 0.f}};

    const size_t tbase = ((size_t)(b * NH + h) * NTILES) * TILE_U4;

    for (int kt = 0; kt < NTILES; kt++) {
        __syncthreads();
        const size_t tb = tbase + (size_t)kt * TILE_U4;
#pragma unroll
        for (int i = 0; i < 4; i++) {
            int idx = tid + 128 * i;      // 512 uint4 per array
            int row = idx >> 3, ch = idx & 7;
            int so = row * SMSTRIDE + ch * 8;
            *(uint4*)&Khi[so] = g_khi4[tb + idx];
            *(uint4*)&Klo[so] = g_klo4[tb + idx];
            *(uint4*)&Vhi[so] = g_vhi4[tb + idx];
            *(uint4*)&Vlo[so] = g_vlo4[tb + idx];
        }
        __syncthreads();

        // S = Q @ K^T: each K fragment feeds both m-blocks.
        float s[2][8][4];
#pragma unroll
        for (int jn = 0; jn < 8; jn++) {
#pragma unroll
            for (int i = 0; i < 4; i++) { s[0][jn][i] = 0.f; s[1][jn][i] = 0.f; }
            const uint2* krh = (const uint2*)&Khi[(jn * 8 + g) * SMSTRIDE];
            const uint2* krl = (const uint2*)&Klo[(jn * 8 + g) * SMSTRIDE];
#pragma unroll
            for (int c = 0; c < 4; c++) {
                uint2 bh_ = krh[c * 4 + tig];
                uint2 bl_ = krl[c * 4 + tig];
                mma_bf16(s[0][jn], qhi[0][c], bh_);
                mma_bf16(s[0][jn], qlo[0][c], bh_);
                mma_bf16(s[0][jn], qhi[0][c], bl_);
                mma_bf16(s[1][jn], qhi[1][c], bh_);
                mma_bf16(s[1][jn], qlo[1][c], bh_);
                mma_bf16(s[1][jn], qhi[1][c], bl_);
            }
        }

        // Online softmax per m-block (log2 domain)
        unsigned phi[2][4][4], plo[2][4][4];
#pragma unroll
        for (int mb = 0; mb < 2; mb++) {
            float rmax0 = s[mb][0][0], rmax1 = s[mb][0][2];
#pragma unroll
            for (int jn = 0; jn < 8; jn++) {
                rmax0 = fmaxf(rmax0, fmaxf(s[mb][jn][0], s[mb][jn][1]));
                rmax1 = fmaxf(rmax1, fmaxf(s[mb][jn][2], s[mb][jn][3]));
            }
            rmax0 = fmaxf(rmax0, __shfl_xor_sync(0xffffffffu, rmax0, 1));
            rmax0 = fmaxf(rmax0, __shfl_xor_sync(0xffffffffu, rmax0, 2));
            rmax1 = fmaxf(rmax1, __shfl_xor_sync(0xffffffffu, rmax1, 1));
            rmax1 = fmaxf(rmax1, __shfl_xor_sync(0xffffffffu, rmax1, 2));

            float mn0 = fmaxf(mst[mb][0], rmax0);
            float mn1 = fmaxf(mst[mb][1], rmax1);
            float corr0 = fast_exp2(mst[mb][0] - mn0);
            float corr1 = fast_exp2(mst[mb][1] - mn1);
            mst[mb][0] = mn0; mst[mb][1] = mn1;

            float ps0 = 0.f, ps1 = 0.f;
#pragma unroll
            for (int jn = 0; jn < 8; jn++) {
                s[mb][jn][0] = fast_exp2(s[mb][jn][0] - mn0);
                s[mb][jn][1] = fast_exp2(s[mb][jn][1] - mn0);
                s[mb][jn][2] = fast_exp2(s[mb][jn][2] - mn1);
                s[mb][jn][3] = fast_exp2(s[mb][jn][3] - mn1);
                ps0 += s[mb][jn][0] + s[mb][jn][1];
                ps1 += s[mb][jn][2] + s[mb][jn][3];
            }
            lst[mb][0] = lst[mb][0] * corr0 + ps0;
            lst[mb][1] = lst[mb][1] * corr1 + ps1;
#pragma unroll
            for (int nt = 0; nt < 8; nt++) {
                o[mb][nt][0] *= corr0;
                o[mb][nt][1] *= corr0;
                o[mb][nt][2] *= corr1;
                o[mb][nt][3] *= corr1;
            }
            // P -> bf16 hi/lo A-fragments (k16 layout matches accumulator)
#pragma unroll
            for (int c = 0; c < 4; c++) {
                pack_split(s[mb][2*c][0],   s[mb][2*c][1],   phi[mb][c][0], plo[mb][c][0]);
                pack_split(s[mb][2*c][2],   s[mb][2*c][3],   phi[mb][c][1], plo[mb][c][1]);
                pack_split(s[mb][2*c+1][0], s[mb][2*c+1][1], phi[mb][c][2], plo[mb][c][2]);
                pack_split(s[mb][2*c+1][2], s[mb][2*c+1][3], phi[mb][c][3], plo[mb][c][3]);
            }
        }

        // O += P @ V: each V fragment feeds both m-blocks.
#pragma unroll
        for (int nt = 0; nt < 8; nt++) {
            const uint2* vrh = (const uint2*)&Vhi[(nt * 8 + g) * SMSTRIDE];
            const uint2* vrl = (const uint2*)&Vlo[(nt * 8 + g) * SMSTRIDE];
#pragma unroll
            for (int c = 0; c < 4; c++) {
                uint2 bh_ = vrh[c * 4 + tig];
                uint2 bl_ = vrl[c * 4 + tig];
                mma_bf16(o[0][nt], phi[0][c], bh_);
                mma_bf16(o[0][nt], plo[0][c], bh_);
                mma_bf16(o[0][nt], phi[0][c], bl_);
                mma_bf16(o[1][nt], phi[1][c], bh_);
                mma_bf16(o[1][nt], plo[1][c], bh_);
                mma_bf16(o[1][nt], phi[1][c], bl_);
            }
        }
    }

    // Epilogue: normalize and write DIRECTLY into packed-A layout for the
    // output projection. mt = global 128-row tile; mb_pack = 2w+mb;
    // ki = 2h+half; nt = half*4 + ks*2 + {0,1} maps cols to k-slab slots.
    const int mt = b * (SEQ / 128) + blockIdx.x;
#pragma unroll
    for (int mb = 0; mb < 2; mb++) {
        float li0 = lst[mb][0], li1 = lst[mb][1];
        li0 += __shfl_xor_sync(0xffffffffu, li0, 1);
        li0 += __shfl_xor_sync(0xffffffffu, li0, 2);
        li1 += __shfl_xor_sync(0xffffffffu, li1, 1);
        li1 += __shfl_xor_sync(0xffffffffu, li1, 2);
        const float inv0 = 1.f / li0;
        const float inv1 = 1.f / li1;
        const int mbp = 2 * w + mb;
#pragma unroll
        for (int half = 0; half < 2; half++) {
            const int ki = 2 * h + half;
            uint4* dst = g_apack + ((size_t)(mt * NKI + ki)) * 1024
                                 + mbp * 64 + lane;
#pragma unroll
            for (int ks = 0; ks < 2; ks++) {
                const int nt = half * 4 + ks * 2;
                uint4 hi, lo;
                pack_split(o[mb][nt][0] * inv0,   o[mb][nt][1] * inv0,   hi.x, lo.x);
                pack_split(o[mb][nt][2] * inv1,   o[mb][nt][3] * inv1,   hi.y, lo.y);
                pack_split(o[mb][nt+1][0] * inv0, o[mb][nt+1][1] * inv0, hi.z, lo.z);
                pack_split(o[mb][nt+1][2] * inv1, o[mb][nt+1][3] * inv1, hi.w, lo.w);
                dst[ks * 32]       = hi;
                dst[ks * 32 + 512] = lo;
            }
        }
    }
}

// ---------------------------------------------------------------------------
extern "C" void kernel_launch(void* const* d_in, const int* in_sizes, int n_in,
                              void* d_out, int out_size)
{
    const float* hidden = (const float*)d_in[0];
    const float* rot    = (const float*)d_in[1];
    const float* w_qkv  = (const float*)d_in[2];
    const float* b_qkv  = (const float*)d_in[3];
    const float* nqw    = (const float*)d_in[4];
    const float* nkw    = (const float*)d_in[5];
    const float* w_out  = (const float*)d_in[6];
    const float* b_out  = (const float*)d_in[7];
    const float* hks    = (const float*)d_in[8];
    const int*   ocl    = (const int*)d_in[9];
    float* out = (float*)d_out;

    static float *p_qkv = nullptr, *p_q = nullptr, *p_k = nullptr,
                 *p_v = nullptr;
    static uint4 *p_bq = nullptr, *p_bo = nullptr;
    if (!p_qkv) {
        cudaGetSymbolAddress((void**)&p_qkv,  g_qkv);
        cudaGetSymbolAddress((void**)&p_q,    g_q);
        cudaGetSymbolAddress((void**)&p_k,    g_k);
        cudaGetSymbolAddress((void**)&p_v,    g_v);
        cudaGetSymbolAddress((void**)&p_bq,   g_bpack_qkv);
        cudaGetSymbolAddress((void**)&p_bo,   g_bpack_out);
    }

    // 1) Pack operands
    pack_b_kernel<<<dim3(NKI, QKV3 / 128), 256>>>(w_qkv, p_bq, QKV3);
    pack_b_kernel<<<dim3(NKI, DIMM / 128), 256>>>(w_out, p_bo, DIMM);
    pack_a_kernel<<<dim3(NKI, ROWS / 128), 256>>>(hidden);

    // 2) QKV projection (bf16x3 tensor cores)
    gemm_bf16x3<<<dim3(QKV3 / 128, ROWS / 128), 256>>>(p_bq, b_qkv, p_qkv, QKV3);

    // 3) RMSNorm + RoPE + history scale + transpose
    preprocess_kernel<<<ROWS, 256>>>(p_qkv, rot, nqw, nkw, hks, ocl,
                                     p_q, p_k, p_v);

    // 4) Pack K,V for attention
    pack_kv_kernel<<<dim3(NTILES, NH, BATCH), 256>>>(p_k, p_v);

    // 5) Attention -> writes packed A (g_apack) directly
    attn_tc_kernel<<<dim3(SEQ / 128, NH, BATCH), 128>>>(p_q);

    // 6) Output projection (bf16x3 tensor cores)
    gemm_bf16x3<<<dim3(DIMM / 128, ROWS / 128), 256>>>(p_bo, b_out, out, DIMM);
}